// round 1
// baseline (speedup 1.0000x reference)
#include <cuda_runtime.h>
#include <cuda_bf16.h>
#include <math.h>

#define BATCH 128
#define SGRID 32
#define CELLS 1024          // 32*32
#define NODES 1025          // + meta
#define FDIM  128
#define NTOT  (BATCH*NODES) // 131200

// ---------------- scratch (no allocation allowed) ----------------
__device__ float g_x0[(size_t)NTOT*FDIM];
__device__ float g_x1[(size_t)NTOT*FDIM];
__device__ float g_ag[(size_t)NTOT*FDIM];
__device__ float g_state[BATCH*640];
__device__ float g_h1[BATCH*512];
__device__ float g_h2[BATCH*512];
__device__ float g_ft[BATCH*256];
__device__ float g_p1[BATCH*256];
__device__ float g_p2[BATCH*256];

__device__ __forceinline__ float elu1(float v){ return v > 0.f ? v : (expf(v) - 1.f); }

// ---------------- init: x = [gmap ; zeros(meta)] ----------------
__global__ void init_x(const float* __restrict__ gmap, float* __restrict__ X){
    int i = blockIdx.x * blockDim.x + threadIdx.x;   // over BATCH*NODES*32 float4s
    int q = i & 31;
    int nb = i >> 5;
    int node = nb % NODES;
    int b = nb / NODES;
    float4 v = make_float4(0.f, 0.f, 0.f, 0.f);
    if (node < CELLS)
        v = ((const float4*)gmap)[((size_t)b * CELLS + node) * 32 + q];
    ((float4*)X)[i] = v;
}

// ---------------- meta aggregation: agg[b,meta] = sum over cells ----------------
__global__ void meta_agg(const float* __restrict__ X, float* __restrict__ A){
    __shared__ float sm[4][FDIM];
    int b = blockIdx.x;
    int t = threadIdx.x;
    int f = t & 127, p = t >> 7;
    const float* xb = X + (size_t)b * NODES * FDIM;
    float s = 0.f;
    int c0 = p * 256;
    #pragma unroll 8
    for (int c = c0; c < c0 + 256; c++) s += xb[c * FDIM + f];
    sm[p][f] = s;
    __syncthreads();
    if (p == 0)
        A[((size_t)b * NODES + CELLS) * FDIM + f] = sm[0][f] + sm[1][f] + sm[2][f] + sm[3][f];
}

// ---------------- cell aggregation: 4-neighbor sum + meta ----------------
__device__ __forceinline__ void f4acc(float4& a, float4 b){ a.x+=b.x; a.y+=b.y; a.z+=b.z; a.w+=b.w; }

__global__ void cell_agg(const float* __restrict__ X, float* __restrict__ A){
    int idx = blockIdx.x * blockDim.x + threadIdx.x;  // BATCH*CELLS*32
    int q    = idx & 31;
    int cell = (idx >> 5) & 1023;
    int b    = idx >> 15;
    int r = cell >> 5, c = cell & 31;
    const float4* xb = (const float4*)(X + (size_t)b * NODES * FDIM);
    float4 s = xb[CELLS * 32 + q];                    // x[meta]
    if (r > 0)     f4acc(s, xb[(cell - 32) * 32 + q]);
    if (r < 31)    f4acc(s, xb[(cell + 32) * 32 + q]);
    if (c > 0)     f4acc(s, xb[(cell - 1) * 32 + q]);
    if (c < 31)    f4acc(s, xb[(cell + 1) * 32 + q]);
    ((float4*)(A + (size_t)b * NODES * FDIM))[cell * 32 + q] = s;
}

// ---------------- GNN layer GEMM: Y = elu(X@Ws + AG@Wn + b) ----------------
// M = NTOT, N = K = 128. Block tile 64x128, 256 threads, 8x4 per thread.
__global__ void __launch_bounds__(256) gnn_gemm(
    const float* __restrict__ X, const float* __restrict__ AG,
    const float* __restrict__ Ws, const float* __restrict__ Wn,
    const float* __restrict__ bias, float* __restrict__ Y)
{
    __shared__ float sX[16][68];   // [k][m] transposed, padded
    __shared__ float sA[16][68];
    __shared__ float sW[16][128];
    __shared__ float sN[16][128];

    int t  = threadIdx.x;
    int tx = t & 31;    // n group  (n = tx*4)
    int ty = t >> 5;    // m group  (m = ty*8), == warp id -> broadcast a-loads
    size_t rowBase = (size_t)blockIdx.x * 64;

    float acc[8][4];
    #pragma unroll
    for (int i = 0; i < 8; i++)
        #pragma unroll
        for (int j = 0; j < 4; j++) acc[i][j] = 0.f;

    int arow = t >> 2, acg = t & 3;          // A tile load: 64 rows x 16 k
    int wk   = t >> 5, wn0 = (t & 31) * 4;   // W tile load: 8 k-rows per pass

    for (int kk = 0; kk < 128; kk += 16) {
        float4 vx = *(const float4*)(X  + (rowBase + arow) * FDIM + kk + acg * 4);
        float4 va = *(const float4*)(AG + (rowBase + arow) * FDIM + kk + acg * 4);
        sX[acg*4+0][arow] = vx.x; sX[acg*4+1][arow] = vx.y;
        sX[acg*4+2][arow] = vx.z; sX[acg*4+3][arow] = vx.w;
        sA[acg*4+0][arow] = va.x; sA[acg*4+1][arow] = va.y;
        sA[acg*4+2][arow] = va.z; sA[acg*4+3][arow] = va.w;
        #pragma unroll
        for (int kh = 0; kh < 2; kh++) {
            int k = wk + kh * 8;
            *(float4*)&sW[k][wn0] = *(const float4*)(Ws + (kk + k) * 128 + wn0);
            *(float4*)&sN[k][wn0] = *(const float4*)(Wn + (kk + k) * 128 + wn0);
        }
        __syncthreads();
        #pragma unroll
        for (int k = 0; k < 16; k++) {
            float a[8], a2[8], b[4], b2[4];
            #pragma unroll
            for (int i = 0; i < 8; i++) { a[i] = sX[k][ty*8+i]; a2[i] = sA[k][ty*8+i]; }
            #pragma unroll
            for (int j = 0; j < 4; j++) { b[j] = sW[k][tx*4+j]; b2[j] = sN[k][tx*4+j]; }
            #pragma unroll
            for (int i = 0; i < 8; i++)
                #pragma unroll
                for (int j = 0; j < 4; j++)
                    acc[i][j] += a[i]*b[j] + a2[i]*b2[j];
        }
        __syncthreads();
    }

    #pragma unroll
    for (int i = 0; i < 8; i++) {
        size_t row = rowBase + ty*8 + i;
        float4 o;
        o.x = elu1(acc[i][0] + bias[tx*4+0]);
        o.y = elu1(acc[i][1] + bias[tx*4+1]);
        o.z = elu1(acc[i][2] + bias[tx*4+2]);
        o.w = elu1(acc[i][3] + bias[tx*4+3]);
        *(float4*)(Y + row * FDIM + tx*4) = o;
    }
}

// ---------------- gather 5 cells (replicates reference's stride-32 index into 34-wide pad) ----------------
__global__ void gather_state(const float* __restrict__ X, const int* __restrict__ pos,
                             float* __restrict__ state)
{
    int b = blockIdx.x;
    int f = threadIdx.x;   // 128
    int r = pos[2*b + 0];
    int c = pos[2*b + 1];
    const int dr[5] = {-1, 0, 1, 0, 0};
    const int dc[5] = { 0,-1, 0, 1, 0};
    #pragma unroll
    for (int o = 0; o < 5; o++) {
        int j  = (r + dr[o] + 1) * 32 + (c + dc[o] + 1);  // NOTE: stride 32 into 34-wide padded grid (reference quirk)
        int jr = j / 34, jc = j % 34;
        float v = 0.f;
        if (jr >= 1 && jr <= 32 && jc >= 1 && jc <= 32) {
            int cell = (jr - 1) * 32 + (jc - 1);
            v = X[((size_t)b * NODES + cell) * FDIM + f];
        }
        state[b * 640 + o * FDIM + f] = v;
    }
}

// ---------------- small MLP GEMM: C = elu(A@W + b), block 64x64, TM=TN=4 ----------------
template<bool ELU>
__global__ void __launch_bounds__(256) mlp_gemm(
    const float* __restrict__ A, const float* __restrict__ W,
    const float* __restrict__ bias, float* __restrict__ C, int K, int N)
{
    __shared__ float sAm[64][16];
    __shared__ float sWm[16][64];
    int t = threadIdx.x;
    int tx = t & 15;   // n = tx*4
    int ty = t >> 4;   // m = ty*4
    int m0 = blockIdx.y * 64;
    int n0 = blockIdx.x * 64;

    float acc[4][4];
    #pragma unroll
    for (int i = 0; i < 4; i++)
        #pragma unroll
        for (int j = 0; j < 4; j++) acc[i][j] = 0.f;

    int arow = t >> 2, acg = t & 3;
    int wk = t >> 4, wn = (t & 15) * 4;

    for (int kk = 0; kk < K; kk += 16) {
        *(float4*)&sAm[arow][acg*4] = *(const float4*)(A + (size_t)(m0 + arow) * K + kk + acg*4);
        *(float4*)&sWm[wk][wn]      = *(const float4*)(W + (size_t)(kk + wk) * N + n0 + wn);
        __syncthreads();
        #pragma unroll
        for (int k = 0; k < 16; k++) {
            float a[4], b[4];
            #pragma unroll
            for (int i = 0; i < 4; i++) a[i] = sAm[ty*4+i][k];
            #pragma unroll
            for (int j = 0; j < 4; j++) b[j] = sWm[k][tx*4+j];
            #pragma unroll
            for (int i = 0; i < 4; i++)
                #pragma unroll
                for (int j = 0; j < 4; j++)
                    acc[i][j] += a[i] * b[j];
        }
        __syncthreads();
    }

    #pragma unroll
    for (int i = 0; i < 4; i++) {
        #pragma unroll
        for (int j = 0; j < 4; j++) {
            float v = acc[i][j] + bias[n0 + tx*4 + j];
            if (ELU) v = elu1(v);
            C[(size_t)(m0 + ty*4 + i) * N + n0 + tx*4 + j] = v;
        }
    }
}

// ---------------- logits + mask ----------------
__global__ void logits_k(const float* __restrict__ P2, const float* __restrict__ W,
                         const float* __restrict__ bias, const int* __restrict__ mask,
                         float* __restrict__ out)
{
    int b = blockIdx.x;
    int a = threadIdx.x;
    if (a >= 19) return;
    float s = bias[a];
    const float* p = P2 + b * 256;
    #pragma unroll 8
    for (int k = 0; k < 256; k++) s += p[k] * W[k * 19 + a];
    int m = mask[b * 19 + a];
    out[b * 19 + a] = s + (m > 0 ? 0.f : -3.4028234663852886e38f);
}

// ---------------- launch ----------------
extern "C" void kernel_launch(void* const* d_in, const int* in_sizes, int n_in,
                              void* d_out, int out_size)
{
    const float* gmap  = (const float*)d_in[0];
    const int*   pos   = (const int*)  d_in[1];
    const int*   amask = (const int*)  d_in[2];
    const float* Ws    = (const float*)d_in[3];
    const float* Wn    = (const float*)d_in[4];
    const float* bs    = (const float*)d_in[5];
    const float* W_d1  = (const float*)d_in[6];
    const float* b_d1  = (const float*)d_in[7];
    const float* W_d2  = (const float*)d_in[8];
    const float* b_d2  = (const float*)d_in[9];
    const float* W_d3  = (const float*)d_in[10];
    const float* b_d3  = (const float*)d_in[11];
    const float* W_p1  = (const float*)d_in[12];
    const float* b_p1  = (const float*)d_in[13];
    const float* W_p2  = (const float*)d_in[14];
    const float* b_p2  = (const float*)d_in[15];
    const float* W_p3  = (const float*)d_in[16];
    const float* b_p3  = (const float*)d_in[17];
    float* out = (float*)d_out;

    float *x0, *x1, *ag, *st, *h1, *h2, *ft, *p1, *p2;
    cudaGetSymbolAddress((void**)&x0, g_x0);
    cudaGetSymbolAddress((void**)&x1, g_x1);
    cudaGetSymbolAddress((void**)&ag, g_ag);
    cudaGetSymbolAddress((void**)&st, g_state);
    cudaGetSymbolAddress((void**)&h1, g_h1);
    cudaGetSymbolAddress((void**)&h2, g_h2);
    cudaGetSymbolAddress((void**)&ft, g_ft);
    cudaGetSymbolAddress((void**)&p1, g_p1);
    cudaGetSymbolAddress((void**)&p2, g_p2);

    // init x = [gmap ; zeros meta]
    init_x<<<(BATCH * NODES * 32) / 256, 256>>>(gmap, x0);

    float* cur = x0;
    float* nxt = x1;
    for (int l = 0; l < 3; l++) {
        meta_agg<<<BATCH, 512>>>(cur, ag);
        cell_agg<<<(BATCH * CELLS * 32) / 256, 256>>>(cur, ag);
        gnn_gemm<<<NTOT / 64, 256>>>(cur, ag, Ws + l * 128 * 128, Wn + l * 128 * 128,
                                     bs + l * 128, nxt);
        float* tmp = cur; cur = nxt; nxt = tmp;
    }

    gather_state<<<BATCH, 128>>>(cur, pos, st);

    mlp_gemm<true><<<dim3(8, 2), 256>>>(st, W_d1, b_d1, h1, 640, 512);
    mlp_gemm<true><<<dim3(8, 2), 256>>>(h1, W_d2, b_d2, h2, 512, 512);
    mlp_gemm<true><<<dim3(4, 2), 256>>>(h2, W_d3, b_d3, ft, 512, 256);
    mlp_gemm<true><<<dim3(4, 2), 256>>>(ft, W_p1, b_p1, p1, 256, 256);
    mlp_gemm<true><<<dim3(4, 2), 256>>>(p1, W_p2, b_p2, p2, 256, 256);

    logits_k<<<BATCH, 32>>>(p2, W_p3, b_p3, amask, out);
}

// round 2
// speedup vs baseline: 1.2901x; 1.2901x over previous
#include <cuda_runtime.h>
#include <cuda_bf16.h>
#include <math.h>

#define BATCH 128
#define SGRID 32
#define CELLS 1024          // 32*32
#define NODES 1025          // + meta
#define FDIM  128
#define NTOT  (BATCH*NODES) // 131200

typedef unsigned long long u64;
union F2 { u64 u; float2 f; };

__device__ __forceinline__ u64 pack2(float lo, float hi){
    u64 r; asm("mov.b64 %0, {%1, %2};" : "=l"(r) : "f"(lo), "f"(hi)); return r;
}
__device__ __forceinline__ void ffma2(u64& d, u64 a, u64 b){
    asm("fma.rn.f32x2 %0, %1, %2, %0;" : "+l"(d) : "l"(a), "l"(b));
}

// ---------------- scratch (no allocation allowed) ----------------
__device__ float g_x0[(size_t)NTOT*FDIM];
__device__ float g_x1[(size_t)NTOT*FDIM];
__device__ float g_magg[BATCH*FDIM];
__device__ float g_state[BATCH*640];
__device__ float g_h1[BATCH*512];
__device__ float g_h2[BATCH*512];
__device__ float g_ft[BATCH*256];
__device__ float g_p1[BATCH*256];
__device__ float g_p2[BATCH*256];

__device__ __forceinline__ float elu1(float v){ return v > 0.f ? v : (expf(v) - 1.f); }

// ---------------- init: x = [gmap ; zeros(meta)] ----------------
__global__ void init_x(const float* __restrict__ gmap, float* __restrict__ X){
    int i = blockIdx.x * blockDim.x + threadIdx.x;   // over BATCH*NODES*32 float4s
    int q = i & 31;
    int nb = i >> 5;
    int node = nb % NODES;
    int b = nb / NODES;
    float4 v = make_float4(0.f, 0.f, 0.f, 0.f);
    if (node < CELLS)
        v = ((const float4*)gmap)[((size_t)b * CELLS + node) * 32 + q];
    ((float4*)X)[i] = v;
}

// ---------------- meta aggregation: MAgg[b] = sum over cells of x ----------------
__global__ void meta_agg(const float* __restrict__ X, float* __restrict__ MAgg){
    __shared__ float sm[4][FDIM];
    int b = blockIdx.x;
    int t = threadIdx.x;
    int f = t & 127, p = t >> 7;
    const float* xb = X + (size_t)b * NODES * FDIM;
    float s = 0.f;
    int c0 = p * 256;
    #pragma unroll 8
    for (int c = c0; c < c0 + 256; c++) s += xb[c * FDIM + f];
    sm[p][f] = s;
    __syncthreads();
    if (p == 0)
        MAgg[b * FDIM + f] = sm[0][f] + sm[1][f] + sm[2][f] + sm[3][f];
}

__device__ __forceinline__ void f4acc(float4& a, float4 b){ a.x+=b.x; a.y+=b.y; a.z+=b.z; a.w+=b.w; }

// ---------------- GNN layer GEMM, agg fused into tile load ----------------
// Y = elu(X@Ws + AGG(X)@Wn + b);  M = NTOT, N = K = 128.
// Block tile 64x128, 256 threads, 8x4 per thread, f32x2 packed FMA.
__global__ void __launch_bounds__(256) gnn_gemm(
    const float* __restrict__ X, const float* __restrict__ MAgg,
    const float* __restrict__ Ws, const float* __restrict__ Wn,
    const float* __restrict__ bias, float* __restrict__ Y)
{
    __shared__ float sX[16][68];   // [k][m] transposed, padded (272B rows, 16B aligned)
    __shared__ float sA[16][68];
    __shared__ float sW[16][128];
    __shared__ float sN[16][128];

    int t  = threadIdx.x;
    int tx = t & 31;    // n group  (n = tx*4)
    int ty = t >> 5;    // m group  (m = ty*8)
    size_t rowBase = (size_t)blockIdx.x * 64;

    u64 acc[4][4];      // [m-pair][n], each u64 = rows (ty*8+2ip, +1)
    #pragma unroll
    for (int i = 0; i < 4; i++)
        #pragma unroll
        for (int j = 0; j < 4; j++) acc[i][j] = 0ULL;

    // ---- per-row agg source pointers (computed once) ----
    int arow = t >> 2, acg = t & 3;          // A tile load: 64 rows x 16 k
    int row  = (int)rowBase + arow;
    int b    = row / NODES;
    int node = row - b * NODES;
    const float* xrow = X + (size_t)row * FDIM;
    const float* batchBase = X + (size_t)b * NODES * FDIM;
    bool isMeta = (node == CELLS);
    int r = node >> 5, c = node & 31;
    bool up = (!isMeta) && (r > 0);
    bool dn = (!isMeta) && (r < 31);
    bool lf = (!isMeta) && (c > 0);
    bool rt = (!isMeta) && (c < 31);
    const float* pMetaOrMA = isMeta ? (MAgg + b * FDIM)
                                    : (batchBase + (size_t)CELLS * FDIM);
    const float* pUp = batchBase + (size_t)(node - 32) * FDIM;
    const float* pDn = batchBase + (size_t)(node + 32) * FDIM;
    const float* pLf = batchBase + (size_t)(node - 1) * FDIM;
    const float* pRt = batchBase + (size_t)(node + 1) * FDIM;

    int wk  = t >> 5, wn0 = (t & 31) * 4;    // W tile load

    for (int kk = 0; kk < 128; kk += 16) {
        int off = kk + acg * 4;
        float4 vx = *(const float4*)(xrow + off);
        float4 va = *(const float4*)(pMetaOrMA + off);
        if (up) f4acc(va, *(const float4*)(pUp + off));
        if (dn) f4acc(va, *(const float4*)(pDn + off));
        if (lf) f4acc(va, *(const float4*)(pLf + off));
        if (rt) f4acc(va, *(const float4*)(pRt + off));
        sX[acg*4+0][arow] = vx.x; sX[acg*4+1][arow] = vx.y;
        sX[acg*4+2][arow] = vx.z; sX[acg*4+3][arow] = vx.w;
        sA[acg*4+0][arow] = va.x; sA[acg*4+1][arow] = va.y;
        sA[acg*4+2][arow] = va.z; sA[acg*4+3][arow] = va.w;
        #pragma unroll
        for (int kh = 0; kh < 2; kh++) {
            int k = wk + kh * 8;
            *(float4*)&sW[k][wn0] = *(const float4*)(Ws + (kk + k) * 128 + wn0);
            *(float4*)&sN[k][wn0] = *(const float4*)(Wn + (kk + k) * 128 + wn0);
        }
        __syncthreads();
        #pragma unroll
        for (int k = 0; k < 16; k++) {
            u64 a[4], a2[4];
            #pragma unroll
            for (int ip = 0; ip < 4; ip++) {
                F2 v; v.f = *(const float2*)&sX[k][ty*8 + 2*ip]; a[ip]  = v.u;
                F2 w; w.f = *(const float2*)&sA[k][ty*8 + 2*ip]; a2[ip] = w.u;
            }
            float4 bw = *(const float4*)&sW[k][tx*4];
            float4 bn = *(const float4*)&sN[k][tx*4];
            u64 bwp[4] = { pack2(bw.x,bw.x), pack2(bw.y,bw.y), pack2(bw.z,bw.z), pack2(bw.w,bw.w) };
            u64 bnp[4] = { pack2(bn.x,bn.x), pack2(bn.y,bn.y), pack2(bn.z,bn.z), pack2(bn.w,bn.w) };
            #pragma unroll
            for (int j = 0; j < 4; j++)
                #pragma unroll
                for (int ip = 0; ip < 4; ip++) {
                    ffma2(acc[ip][j], a[ip],  bwp[j]);
                    ffma2(acc[ip][j], a2[ip], bnp[j]);
                }
        }
        __syncthreads();
    }

    float4 bb = *(const float4*)(bias + tx*4);
    #pragma unroll
    for (int ip = 0; ip < 4; ip++) {
        F2 u0, u1, u2, u3;
        u0.u = acc[ip][0]; u1.u = acc[ip][1]; u2.u = acc[ip][2]; u3.u = acc[ip][3];
        size_t r0 = rowBase + ty*8 + 2*ip;
        float4 o0, o1;
        o0.x = elu1(u0.f.x + bb.x); o0.y = elu1(u1.f.x + bb.y);
        o0.z = elu1(u2.f.x + bb.z); o0.w = elu1(u3.f.x + bb.w);
        o1.x = elu1(u0.f.y + bb.x); o1.y = elu1(u1.f.y + bb.y);
        o1.z = elu1(u2.f.y + bb.z); o1.w = elu1(u3.f.y + bb.w);
        *(float4*)(Y + r0 * FDIM + tx*4)       = o0;
        *(float4*)(Y + (r0 + 1) * FDIM + tx*4) = o1;
    }
}

// ---------------- gather 5 cells (replicates reference's stride-32 index into 34-wide pad) ----------------
__global__ void gather_state(const float* __restrict__ X, const int* __restrict__ pos,
                             float* __restrict__ state)
{
    int b = blockIdx.x;
    int f = threadIdx.x;   // 128
    int r = pos[2*b + 0];
    int c = pos[2*b + 1];
    const int dr[5] = {-1, 0, 1, 0, 0};
    const int dc[5] = { 0,-1, 0, 1, 0};
    #pragma unroll
    for (int o = 0; o < 5; o++) {
        int j  = (r + dr[o] + 1) * 32 + (c + dc[o] + 1);  // stride-32 into 34-wide pad (ref quirk)
        int jr = j / 34, jc = j % 34;
        float v = 0.f;
        if (jr >= 1 && jr <= 32 && jc >= 1 && jc <= 32) {
            int cell = (jr - 1) * 32 + (jc - 1);
            v = X[((size_t)b * NODES + cell) * FDIM + f];
        }
        state[b * 640 + o * FDIM + f] = v;
    }
}

// ---------------- small MLP GEMM: C = elu(A@W + b), block 64x64, f32x2 ----------------
template<bool ELU>
__global__ void __launch_bounds__(256) mlp_gemm(
    const float* __restrict__ A, const float* __restrict__ W,
    const float* __restrict__ bias, float* __restrict__ C, int K, int N)
{
    __shared__ float sAm[64][16];
    __shared__ float sWm[16][64];
    int t = threadIdx.x;
    int tx = t & 15;   // n = tx*4
    int ty = t >> 4;   // m = ty*4
    int m0 = blockIdx.y * 64;
    int n0 = blockIdx.x * 64;

    u64 acc[4][2];     // [m][n-pair]
    #pragma unroll
    for (int i = 0; i < 4; i++) { acc[i][0] = 0ULL; acc[i][1] = 0ULL; }

    int arow = t >> 2, acg = t & 3;
    int wk = t >> 4, wn = (t & 15) * 4;

    for (int kk = 0; kk < K; kk += 16) {
        *(float4*)&sAm[arow][acg*4] = *(const float4*)(A + (size_t)(m0 + arow) * K + kk + acg*4);
        *(float4*)&sWm[wk][wn]      = *(const float4*)(W + (size_t)(kk + wk) * N + n0 + wn);
        __syncthreads();
        #pragma unroll
        for (int k = 0; k < 16; k++) {
            F2 b0, b1;
            b0.f = *(const float2*)&sWm[k][tx*4];
            b1.f = *(const float2*)&sWm[k][tx*4 + 2];
            #pragma unroll
            for (int i = 0; i < 4; i++) {
                float av = sAm[ty*4+i][k];
                u64 ap = pack2(av, av);
                ffma2(acc[i][0], ap, b0.u);
                ffma2(acc[i][1], ap, b1.u);
            }
        }
        __syncthreads();
    }

    float4 bb = *(const float4*)(bias + n0 + tx*4);
    #pragma unroll
    for (int i = 0; i < 4; i++) {
        F2 u0, u1; u0.u = acc[i][0]; u1.u = acc[i][1];
        float4 o;
        o.x = u0.f.x + bb.x; o.y = u0.f.y + bb.y;
        o.z = u1.f.x + bb.z; o.w = u1.f.y + bb.w;
        if (ELU) { o.x = elu1(o.x); o.y = elu1(o.y); o.z = elu1(o.z); o.w = elu1(o.w); }
        *(float4*)(C + (size_t)(m0 + ty*4 + i) * N + n0 + tx*4) = o;
    }
}

// ---------------- logits + mask ----------------
__global__ void logits_k(const float* __restrict__ P2, const float* __restrict__ W,
                         const float* __restrict__ bias, const int* __restrict__ mask,
                         float* __restrict__ out)
{
    int b = blockIdx.x;
    int a = threadIdx.x;
    if (a >= 19) return;
    float s = bias[a];
    const float* p = P2 + b * 256;
    #pragma unroll 8
    for (int k = 0; k < 256; k++) s += p[k] * W[k * 19 + a];
    int m = mask[b * 19 + a];
    out[b * 19 + a] = s + (m > 0 ? 0.f : -3.4028234663852886e38f);
}

// ---------------- launch ----------------
extern "C" void kernel_launch(void* const* d_in, const int* in_sizes, int n_in,
                              void* d_out, int out_size)
{
    const float* gmap  = (const float*)d_in[0];
    const int*   pos   = (const int*)  d_in[1];
    const int*   amask = (const int*)  d_in[2];
    const float* Ws    = (const float*)d_in[3];
    const float* Wn    = (const float*)d_in[4];
    const float* bs    = (const float*)d_in[5];
    const float* W_d1  = (const float*)d_in[6];
    const float* b_d1  = (const float*)d_in[7];
    const float* W_d2  = (const float*)d_in[8];
    const float* b_d2  = (const float*)d_in[9];
    const float* W_d3  = (const float*)d_in[10];
    const float* b_d3  = (const float*)d_in[11];
    const float* W_p1  = (const float*)d_in[12];
    const float* b_p1  = (const float*)d_in[13];
    const float* W_p2  = (const float*)d_in[14];
    const float* b_p2  = (const float*)d_in[15];
    const float* W_p3  = (const float*)d_in[16];
    const float* b_p3  = (const float*)d_in[17];
    float* out = (float*)d_out;

    float *x0, *x1, *ma, *st, *h1, *h2, *ft, *p1, *p2;
    cudaGetSymbolAddress((void**)&x0, g_x0);
    cudaGetSymbolAddress((void**)&x1, g_x1);
    cudaGetSymbolAddress((void**)&ma, g_magg);
    cudaGetSymbolAddress((void**)&st, g_state);
    cudaGetSymbolAddress((void**)&h1, g_h1);
    cudaGetSymbolAddress((void**)&h2, g_h2);
    cudaGetSymbolAddress((void**)&ft, g_ft);
    cudaGetSymbolAddress((void**)&p1, g_p1);
    cudaGetSymbolAddress((void**)&p2, g_p2);

    init_x<<<(BATCH * NODES * 32) / 256, 256>>>(gmap, x0);

    float* cur = x0;
    float* nxt = x1;
    for (int l = 0; l < 3; l++) {
        meta_agg<<<BATCH, 512>>>(cur, ma);
        gnn_gemm<<<NTOT / 64, 256>>>(cur, ma, Ws + l * 128 * 128, Wn + l * 128 * 128,
                                     bs + l * 128, nxt);
        float* tmp = cur; cur = nxt; nxt = tmp;
    }

    gather_state<<<BATCH, 128>>>(cur, pos, st);

    mlp_gemm<true><<<dim3(8, 2), 256>>>(st, W_d1, b_d1, h1, 640, 512);
    mlp_gemm<true><<<dim3(8, 2), 256>>>(h1, W_d2, b_d2, h2, 512, 512);
    mlp_gemm<true><<<dim3(4, 2), 256>>>(h2, W_d3, b_d3, ft, 512, 256);
    mlp_gemm<true><<<dim3(4, 2), 256>>>(ft, W_p1, b_p1, p1, 256, 256);
    mlp_gemm<true><<<dim3(4, 2), 256>>>(p1, W_p2, b_p2, p2, 256, 256);

    logits_k<<<BATCH, 32>>>(p2, W_p3, b_p3, amask, out);
}

// round 5
// speedup vs baseline: 1.9547x; 1.5151x over previous
#include <cuda_runtime.h>
#include <cuda_bf16.h>
#include <math.h>
#include <stdint.h>

#define BATCH 128
#define CELLS 1024
#define NODES 1025
#define FDIM  128
#define NTOT  (BATCH*NODES)   // 131200

typedef unsigned long long u64;
union F2 { u64 u; float2 f; };

__device__ __forceinline__ u64 pack2(float lo, float hi){
    u64 r; asm("mov.b64 %0, {%1, %2};" : "=l"(r) : "f"(lo), "f"(hi)); return r;
}
__device__ __forceinline__ void ffma2(u64& d, u64 a, u64 b){
    asm("fma.rn.f32x2 %0, %1, %2, %0;" : "+l"(d) : "l"(a), "l"(b));
}
__device__ __forceinline__ float elu1(float v){ return v > 0.f ? v : (expf(v) - 1.f); }

__device__ __forceinline__ uint32_t smem_u32(const void* p){
    uint32_t a; asm("{ .reg .u64 t; cvta.to.shared.u64 t, %1; cvt.u32.u64 %0, t; }" : "=r"(a) : "l"(p));
    return a;
}

// ---------------- scratch ----------------
__device__ __nv_bfloat16 g_xb0[(size_t)NTOT*FDIM];
__device__ __nv_bfloat16 g_xb1[(size_t)NTOT*FDIM];
__device__ __nv_bfloat16 g_magg[BATCH*FDIM];
__device__ __nv_bfloat16 g_wt[3*128*256];   // [l][n=128][k=256]: k<128 Ws^T, k>=128 Wn^T
__device__ float g_state[BATCH*640];
__device__ float g_h1[BATCH*512];
__device__ float g_h2[BATCH*512];
__device__ float g_ft[BATCH*256];
__device__ float g_p1[BATCH*256];
__device__ float g_p2[BATCH*256];

// ---------------- weight prep ----------------
__global__ void prep_wt(const float* __restrict__ Ws, const float* __restrict__ Wn,
                        __nv_bfloat16* __restrict__ Wt){
    int idx = blockIdx.x * blockDim.x + threadIdx.x;   // 3*128*256
    int l = idx >> 15;
    int r = idx & 32767;
    int n = r >> 8;
    int k = r & 255;
    float v = (k < 128) ? Ws[l*16384 + k*128 + n] : Wn[l*16384 + (k-128)*128 + n];
    Wt[idx] = __float2bfloat16(v);
}

// ---------------- init: x = bf16(gmap), meta row zero ----------------
__global__ void init_x(const float* __restrict__ gmap, __nv_bfloat16* __restrict__ X){
    int i = blockIdx.x * blockDim.x + threadIdx.x;   // NTOT*16 uint4 chunks (8 bf16)
    int q = i & 15;
    int nb = i >> 4;
    int node = nb % NODES;
    int b = nb / NODES;
    uint4 o = make_uint4(0,0,0,0);
    if (node < CELLS) {
        const float4* g = (const float4*)gmap + (((size_t)(b*CELLS + node))*128 + q*8)/4;
        float4 v0 = g[0], v1 = g[1];
        __nv_bfloat162* ho = (__nv_bfloat162*)&o;
        ho[0] = __float22bfloat162_rn(make_float2(v0.x, v0.y));
        ho[1] = __float22bfloat162_rn(make_float2(v0.z, v0.w));
        ho[2] = __float22bfloat162_rn(make_float2(v1.x, v1.y));
        ho[3] = __float22bfloat162_rn(make_float2(v1.z, v1.w));
    }
    ((uint4*)X)[i] = o;
}

// ---------------- meta aggregation: MAgg[b] = sum_cells x ----------------
__global__ void meta_agg(const __nv_bfloat16* __restrict__ X, __nv_bfloat16* __restrict__ MAgg){
    __shared__ float2 sm[16][64];
    int b = blockIdx.x, t = threadIdx.x;          // 1024 threads
    int f2 = t & 63, p = t >> 6;                  // 16 partitions x 64 cells
    const __nv_bfloat162* xb = (const __nv_bfloat162*)(X + (size_t)b * NODES * FDIM);
    float2 s = make_float2(0.f, 0.f);
    int c0 = p * 64;
    #pragma unroll 8
    for (int c = c0; c < c0 + 64; c++) {
        float2 v = __bfloat1622float2(xb[c*64 + f2]);
        s.x += v.x; s.y += v.y;
    }
    sm[p][f2] = s;
    __syncthreads();
    if (p == 0) {
        s = sm[0][f2];
        #pragma unroll
        for (int i = 1; i < 16; i++) { s.x += sm[i][f2].x; s.y += sm[i][f2].y; }
        ((__nv_bfloat162*)MAgg)[b*64 + f2] = __float22bfloat162_rn(s);
    }
}

// ---------------- GNN layer: bf16 mma.sync, Y = elu([x|agg] @ Wt^T + bias) ----------------
// CTA: M=64, N=128, K=256. 256 threads = 8 warps (2m x 4n), warp tile 32x32.
#define STRB 528                    // smem row stride bytes (264 bf16)
#define SMA_OFF 0
#define SMB_OFF (64*STRB)           // 33792
#define GNN_SMEM (64*STRB + 128*STRB)   // 101376

__device__ __forceinline__ void bf8_accum(uint4 v, float2* s){
    __nv_bfloat162* h = (__nv_bfloat162*)&v;
    #pragma unroll
    for (int i = 0; i < 4; i++) {
        float2 f = __bfloat1622float2(h[i]);
        s[i].x += f.x; s[i].y += f.y;
    }
}

__global__ void __launch_bounds__(256, 2) gnn_mma(
    const __nv_bfloat16* __restrict__ X, const __nv_bfloat16* __restrict__ MAgg,
    const __nv_bfloat16* __restrict__ Wt, const float* __restrict__ bias,
    __nv_bfloat16* __restrict__ Y)
{
    extern __shared__ char smem[];
    uint32_t sb = smem_u32(smem);
    int t = threadIdx.x;
    int wid = t >> 5, lane = t & 31;
    int m0cta = blockIdx.x * 64;

    // ---- B tile: Wt[128][256] -> sB[n*STRB + k*2]; thread t: row n=t>>1, half h=t&1 (128 bf16 = 16 uint4) ----
    {
        int n = t >> 1, h = t & 1;
        const uint4* src = (const uint4*)(Wt + (size_t)n*256 + h*128);
        char* dst = smem + SMB_OFF + n*STRB + h*256;
        #pragma unroll
        for (int j = 0; j < 16; j++) *(uint4*)(dst + j*16) = src[j];
    }

    // ---- A tile: rows m0cta..+63, cols 0-127 = x, 128-255 = agg ----
    if (t < 128) {
        int m = t >> 1, h = t & 1;
        int row = m0cta + m;
        const uint4* src = (const uint4*)(X + (size_t)row * FDIM + h*64);
        char* dst = smem + SMA_OFF + m*STRB + h*128;
        #pragma unroll
        for (int j = 0; j < 8; j++) *(uint4*)(dst + j*16) = src[j];
    } else {
        int tt = t - 128;
        int m = tt >> 1, h = tt & 1;
        int row = m0cta + m;
        int b = row / NODES;
        int node = row - b * NODES;
        const __nv_bfloat16* bBase = X + (size_t)b * NODES * FDIM;
        bool isMeta = (node == CELLS);
        int r = node >> 5, c = node & 31;
        bool up = !isMeta && (r > 0),  dn = !isMeta && (r < 31);
        bool lf = !isMeta && (c > 0),  rt = !isMeta && (c < 31);
        const uint4* p0 = (const uint4*)((isMeta ? (MAgg + b*FDIM) : (bBase + (size_t)CELLS*FDIM)) + h*64);
        const uint4* pU = (const uint4*)(bBase + (size_t)(node - 32)*FDIM + h*64);
        const uint4* pD = (const uint4*)(bBase + (size_t)(node + 32)*FDIM + h*64);
        const uint4* pL = (const uint4*)(bBase + (size_t)(node - 1)*FDIM + h*64);
        const uint4* pR = (const uint4*)(bBase + (size_t)(node + 1)*FDIM + h*64);
        char* dst = smem + SMA_OFF + m*STRB + 256 + h*128;
        #pragma unroll
        for (int j = 0; j < 8; j++) {
            float2 s[4];
            {
                uint4 a0 = p0[j];
                __nv_bfloat162* hh = (__nv_bfloat162*)&a0;
                #pragma unroll
                for (int i = 0; i < 4; i++) s[i] = __bfloat1622float2(hh[i]);
            }
            if (up) bf8_accum(pU[j], s);
            if (dn) bf8_accum(pD[j], s);
            if (lf) bf8_accum(pL[j], s);
            if (rt) bf8_accum(pR[j], s);
            uint4 o;
            __nv_bfloat162* ho = (__nv_bfloat162*)&o;
            #pragma unroll
            for (int i = 0; i < 4; i++) ho[i] = __float22bfloat162_rn(s[i]);
            *(uint4*)(dst + j*16) = o;
        }
    }
    __syncthreads();

    // ---- MMA ----
    int warp_m = wid >> 2;          // 0-1, 32 rows each
    int warp_n = wid & 3;           // 0-3, 32 cols each
    uint32_t saA = sb + SMA_OFF + (warp_m*32 + (lane & 15))*STRB + (lane >> 4)*16;
    uint32_t saB = sb + SMB_OFF + (warp_n*32 + (lane & 7))*STRB + ((lane >> 3) & 1)*16;

    float acc[2][4][4];
    #pragma unroll
    for (int i = 0; i < 2; i++)
        #pragma unroll
        for (int j = 0; j < 4; j++)
            #pragma unroll
            for (int q = 0; q < 4; q++) acc[i][j][q] = 0.f;

    #pragma unroll
    for (int k0 = 0; k0 < 256; k0 += 16) {
        uint32_t a[2][4];
        #pragma unroll
        for (int mf = 0; mf < 2; mf++)
            asm volatile("ldmatrix.sync.aligned.m8n8.x4.shared.b16 {%0,%1,%2,%3}, [%4];"
                : "=r"(a[mf][0]), "=r"(a[mf][1]), "=r"(a[mf][2]), "=r"(a[mf][3])
                : "r"(saA + mf*16*STRB + k0*2));
        uint32_t bfr[4][2];
        #pragma unroll
        for (int nf = 0; nf < 4; nf++)
            asm volatile("ldmatrix.sync.aligned.m8n8.x2.shared.b16 {%0,%1}, [%2];"
                : "=r"(bfr[nf][0]), "=r"(bfr[nf][1])
                : "r"(saB + nf*8*STRB + k0*2));
        #pragma unroll
        for (int mf = 0; mf < 2; mf++)
            #pragma unroll
            for (int nf = 0; nf < 4; nf++)
                asm volatile("mma.sync.aligned.m16n8k16.row.col.f32.bf16.bf16.f32 "
                    "{%0,%1,%2,%3}, {%4,%5,%6,%7}, {%8,%9}, {%0,%1,%2,%3};"
                    : "+f"(acc[mf][nf][0]), "+f"(acc[mf][nf][1]),
                      "+f"(acc[mf][nf][2]), "+f"(acc[mf][nf][3])
                    : "r"(a[mf][0]), "r"(a[mf][1]), "r"(a[mf][2]), "r"(a[mf][3]),
                      "r"(bfr[nf][0]), "r"(bfr[nf][1]));
    }

    // ---- epilogue: bias + elu, bf16 pair stores ----
    int gr = lane >> 2, gc = lane & 3;
    #pragma unroll
    for (int nf = 0; nf < 4; nf++) {
        int col = warp_n*32 + nf*8 + 2*gc;
        float2 bb = *(const float2*)(bias + col);
        #pragma unroll
        for (int mf = 0; mf < 2; mf++) {
            int r0 = m0cta + warp_m*32 + mf*16 + gr;
            float v0 = elu1(acc[mf][nf][0] + bb.x);
            float v1 = elu1(acc[mf][nf][1] + bb.y);
            float v2 = elu1(acc[mf][nf][2] + bb.x);
            float v3 = elu1(acc[mf][nf][3] + bb.y);
            __nv_bfloat162 o0 = __float22bfloat162_rn(make_float2(v0, v1));
            __nv_bfloat162 o1 = __float22bfloat162_rn(make_float2(v2, v3));
            *(__nv_bfloat162*)(Y + (size_t)r0 * FDIM + col)       = o0;
            *(__nv_bfloat162*)(Y + (size_t)(r0 + 8) * FDIM + col) = o1;
        }
    }
}

// ---------------- gather 5 cells (ref's stride-32 index into 34-wide pad) ----------------
__global__ void gather_state(const __nv_bfloat16* __restrict__ X, const int* __restrict__ pos,
                             float* __restrict__ state)
{
    int b = blockIdx.x;
    int f = threadIdx.x;   // 128
    int r = pos[2*b + 0];
    int c = pos[2*b + 1];
    const int dr[5] = {-1, 0, 1, 0, 0};
    const int dc[5] = { 0,-1, 0, 1, 0};
    #pragma unroll
    for (int o = 0; o < 5; o++) {
        int j  = (r + dr[o] + 1) * 32 + (c + dc[o] + 1);
        int jr = j / 34, jc = j % 34;
        float v = 0.f;
        if (jr >= 1 && jr <= 32 && jc >= 1 && jc <= 32) {
            int cell = (jr - 1) * 32 + (jc - 1);
            v = __bfloat162float(X[((size_t)b * NODES + cell) * FDIM + f]);
        }
        state[b * 640 + o * FDIM + f] = v;
    }
}

// ---------------- small MLP GEMM (fp32, f32x2) ----------------
template<bool ELU>
__global__ void __launch_bounds__(256) mlp_gemm(
    const float* __restrict__ A, const float* __restrict__ W,
    const float* __restrict__ bias, float* __restrict__ C, int K, int N)
{
    __shared__ float sAm[64][16];
    __shared__ float sWm[16][64];
    int t = threadIdx.x;
    int tx = t & 15;
    int ty = t >> 4;
    int m0 = blockIdx.y * 64;
    int n0 = blockIdx.x * 64;

    u64 acc[4][2];
    #pragma unroll
    for (int i = 0; i < 4; i++) { acc[i][0] = 0ULL; acc[i][1] = 0ULL; }

    int arow = t >> 2, acg = t & 3;
    int wk = t >> 4, wn = (t & 15) * 4;

    for (int kk = 0; kk < K; kk += 16) {
        *(float4*)&sAm[arow][acg*4] = *(const float4*)(A + (size_t)(m0 + arow) * K + kk + acg*4);
        *(float4*)&sWm[wk][wn]      = *(const float4*)(W + (size_t)(kk + wk) * N + n0 + wn);
        __syncthreads();
        #pragma unroll
        for (int k = 0; k < 16; k++) {
            F2 b0, b1;
            b0.f = *(const float2*)&sWm[k][tx*4];
            b1.f = *(const float2*)&sWm[k][tx*4 + 2];
            #pragma unroll
            for (int i = 0; i < 4; i++) {
                float av = sAm[ty*4+i][k];
                u64 ap = pack2(av, av);
                ffma2(acc[i][0], ap, b0.u);
                ffma2(acc[i][1], ap, b1.u);
            }
        }
        __syncthreads();
    }

    float4 bb = *(const float4*)(bias + n0 + tx*4);
    #pragma unroll
    for (int i = 0; i < 4; i++) {
        F2 u0, u1; u0.u = acc[i][0]; u1.u = acc[i][1];
        float4 o;
        o.x = u0.f.x + bb.x; o.y = u0.f.y + bb.y;
        o.z = u1.f.x + bb.z; o.w = u1.f.y + bb.w;
        if (ELU) { o.x = elu1(o.x); o.y = elu1(o.y); o.z = elu1(o.z); o.w = elu1(o.w); }
        *(float4*)(C + (size_t)(m0 + ty*4 + i) * N + n0 + tx*4) = o;
    }
}

// ---------------- logits + mask ----------------
__global__ void logits_k(const float* __restrict__ P2, const float* __restrict__ W,
                         const float* __restrict__ bias, const int* __restrict__ mask,
                         float* __restrict__ out)
{
    int b = blockIdx.x;
    int a = threadIdx.x;
    if (a >= 19) return;
    float s = bias[a];
    const float* p = P2 + b * 256;
    #pragma unroll 8
    for (int k = 0; k < 256; k++) s += p[k] * W[k * 19 + a];
    int m = mask[b * 19 + a];
    out[b * 19 + a] = s + (m > 0 ? 0.f : -3.4028234663852886e38f);
}

// ---------------- launch ----------------
extern "C" void kernel_launch(void* const* d_in, const int* in_sizes, int n_in,
                              void* d_out, int out_size)
{
    const float* gmap  = (const float*)d_in[0];
    const int*   pos   = (const int*)  d_in[1];
    const int*   amask = (const int*)  d_in[2];
    const float* Ws    = (const float*)d_in[3];
    const float* Wn    = (const float*)d_in[4];
    const float* bs    = (const float*)d_in[5];
    const float* W_d1  = (const float*)d_in[6];
    const float* b_d1  = (const float*)d_in[7];
    const float* W_d2  = (const float*)d_in[8];
    const float* b_d2  = (const float*)d_in[9];
    const float* W_d3  = (const float*)d_in[10];
    const float* b_d3  = (const float*)d_in[11];
    const float* W_p1  = (const float*)d_in[12];
    const float* b_p1  = (const float*)d_in[13];
    const float* W_p2  = (const float*)d_in[14];
    const float* b_p2  = (const float*)d_in[15];
    const float* W_p3  = (const float*)d_in[16];
    const float* b_p3  = (const float*)d_in[17];
    float* out = (float*)d_out;

    __nv_bfloat16 *x0, *x1, *ma, *wt;
    float *st, *h1, *h2, *ft, *p1, *p2;
    cudaGetSymbolAddress((void**)&x0, g_xb0);
    cudaGetSymbolAddress((void**)&x1, g_xb1);
    cudaGetSymbolAddress((void**)&ma, g_magg);
    cudaGetSymbolAddress((void**)&wt, g_wt);
    cudaGetSymbolAddress((void**)&st, g_state);
    cudaGetSymbolAddress((void**)&h1, g_h1);
    cudaGetSymbolAddress((void**)&h2, g_h2);
    cudaGetSymbolAddress((void**)&ft, g_ft);
    cudaGetSymbolAddress((void**)&p1, g_p1);
    cudaGetSymbolAddress((void**)&p2, g_p2);

    cudaFuncSetAttribute(gnn_mma, cudaFuncAttributeMaxDynamicSharedMemorySize, GNN_SMEM);

    prep_wt<<<(3*128*256)/256, 256>>>(Ws, Wn, wt);
    init_x<<<(NTOT*16)/256, 256>>>(gmap, x0);

    __nv_bfloat16* cur = x0;
    __nv_bfloat16* nxt = x1;
    for (int l = 0; l < 3; l++) {
        meta_agg<<<BATCH, 1024>>>(cur, ma);
        gnn_mma<<<NTOT/64, 256, GNN_SMEM>>>(cur, ma, wt + (size_t)l*128*256, bs + l*128, nxt);
        __nv_bfloat16* tmp = cur; cur = nxt; nxt = tmp;
    }

    gather_state<<<BATCH, 128>>>(cur, pos, st);

    mlp_gemm<true><<<dim3(8, 2), 256>>>(st, W_d1, b_d1, h1, 640, 512);
    mlp_gemm<true><<<dim3(8, 2), 256>>>(h1, W_d2, b_d2, h2, 512, 512);
    mlp_gemm<true><<<dim3(4, 2), 256>>>(h2, W_d3, b_d3, ft, 512, 256);
    mlp_gemm<true><<<dim3(4, 2), 256>>>(ft, W_p1, b_p1, p1, 256, 256);
    mlp_gemm<true><<<dim3(4, 2), 256>>>(p1, W_p2, b_p2, p2, 256, 256);

    logits_k<<<BATCH, 32>>>(p2, W_p3, b_p3, amask, out);
}